// round 1
// baseline (speedup 1.0000x reference)
#include <cuda_runtime.h>
#include <cstdint>

// Problem constants (from reference)
#define HMAX 60
#define GDIM 121           // 2*HMAX+1
#define MAX_MULT 5
#define WMIN 0.95f
#define WMAX 1.25f

__device__ __forceinline__ int gcd2(int a, int b) {
    // a,b >= 0
    while (b != 0) { int t = a % b; a = b; b = t; }
    return a;
}

__global__ void __launch_bounds__(256)
expand_harmonics_kernel(const int* __restrict__ asu_id,     // [N]
                        const int* __restrict__ hkl,        // [N,3]
                        const float* __restrict__ wavelength, // [N]
                        const float* __restrict__ dmin,     // [N_ASU]
                        const float* __restrict__ B,        // [N_ASU,3,3]
                        const int* __restrict__ refl_table, // [N_ASU,G,G,G]
                        float* __restrict__ out,            // [30*N] f32
                        int N)
{
    int i = blockIdx.x * blockDim.x + threadIdx.x;
    if (i >= N) return;

    const int asu = asu_id[i];
    const int h = hkl[3 * i + 0];
    const int k = hkl[3 * i + 1];
    const int l = hkl[3 * i + 2];
    const bool mask = (h | k | l) != 0;

    // gcd reduction
    int g = gcd2(gcd2(abs(h), abs(k)), abs(l));
    const int ns = max(g, 1);
    const int h0 = h / ns;   // exact (ns divides each component)
    const int k0 = k / ns;
    const int l0 = l / ns;

    const float wl0 = wavelength[i] * (float)ns;
    const float dmin_g = __ldg(&dmin[asu]);

    // s = B[asu] @ hkl_0
    const float* Ba = B + 9 * asu;
    const float h0f = (float)h0, k0f = (float)k0, l0f = (float)l0;
    const float s0 = __ldg(&Ba[0]) * h0f + __ldg(&Ba[1]) * k0f + __ldg(&Ba[2]) * l0f;
    const float s1 = __ldg(&Ba[3]) * h0f + __ldg(&Ba[4]) * k0f + __ldg(&Ba[5]) * l0f;
    const float s2 = __ldg(&Ba[6]) * h0f + __ldg(&Ba[7]) * k0f + __ldg(&Ba[8]) * l0f;
    const float nrm = __fsqrt_rn(s0 * s0 + s1 * s1 + s2 * s2);
    const float d0  = __fdiv_rn(1.0f, fmaxf(nrm, 1e-6f));

    const float n_max = fminf(floorf(__fdiv_rn(d0, dmin_g)),
                              floorf(__fdiv_rn(wl0, WMIN)));
    const float n_min = floorf(__fdiv_rn(wl0, WMAX)) + 1.0f;

    const long long nll = (long long)N;
    float* out_hkl = out;                      // [N,5,3]
    float* out_wl  = out + 15 * nll;           // [N,5]
    float* out_d   = out + 20 * nll;           // [N,5]
    float* out_rid = out + 25 * nll;           // [N,5]

    const int table_base = asu * (GDIM * GDIM * GDIM);

#pragma unroll
    for (int m = 0; m < MAX_MULT; ++m) {
        float na = n_min + (float)m;
        if (na > n_max) na = 0.0f;
        int ni = (int)na;

        int ha = h0 * ni, ka = k0 * ni, la = l0 * ni;

        // table lookup (invalid -> -1; (0,0,0) entry is -1 by construction)
        int ia = ha + HMAX, ib = ka + HMAX, ic = la + HMAX;
        bool valid = ((unsigned)ia < GDIM) & ((unsigned)ib < GDIM) & ((unsigned)ic < GDIM);
        int rid = -1;
        if (valid) {
            rid = __ldg(&refl_table[table_base + (ia * GDIM + ib) * GDIM + ic]);
        }

        const bool absent = rid < 0;
        float n_inv, wla, dall;
        if (absent) {
            ha = 0; ka = 0; la = 0;
            n_inv = 0.0f;
        } else {
            n_inv = __fdiv_rn(1.0f, fmaxf(na, 1e-6f));
        }
        dall = d0 * n_inv;
        wla  = wl0 * n_inv;

        float ridf = (float)rid;
        if (!mask) {
            ha = 0; ka = 0; la = 0;
            wla = 0.0f; dall = 0.0f; ridf = 0.0f;
        }

        const long long base3 = (long long)i * 15 + m * 3;
        out_hkl[base3 + 0] = (float)ha;
        out_hkl[base3 + 1] = (float)ka;
        out_hkl[base3 + 2] = (float)la;
        const long long base1 = (long long)i * 5 + m;
        out_wl[base1]  = wla;
        out_d[base1]   = dall;
        out_rid[base1] = ridf;
    }
}

extern "C" void kernel_launch(void* const* d_in, const int* in_sizes, int n_in,
                              void* d_out, int out_size)
{
    const int*   asu_id     = (const int*)d_in[0];     // [N,1]
    const int*   hkl        = (const int*)d_in[1];     // [N,3]
    const float* wavelength = (const float*)d_in[2];   // [N,1]
    const float* dmin       = (const float*)d_in[3];   // [N_ASU]
    const float* B          = (const float*)d_in[4];   // [N_ASU,3,3]
    const int*   refl_table = (const int*)d_in[5];     // [N_ASU,G,G,G]

    const int N = in_sizes[0];
    float* out = (float*)d_out;

    const int threads = 256;
    const int blocks = (N + threads - 1) / threads;
    expand_harmonics_kernel<<<blocks, threads>>>(asu_id, hkl, wavelength,
                                                 dmin, B, refl_table, out, N);
}

// round 2
// speedup vs baseline: 2.9588x; 2.9588x over previous
#include <cuda_runtime.h>
#include <cstdint>

#define HMAX 60
#define GDIM 121           // 2*HMAX+1
#define MAX_MULT 5
#define WMIN 0.95f
#define WMAX 1.25f
#define BLK 256

__device__ __forceinline__ int gcd2(int a, int b) {
    while (b != 0) { int t = a % b; a = b; b = t; }
    return a;
}

__global__ void __launch_bounds__(BLK)
expand_harmonics_kernel(const int* __restrict__ asu_id,       // [N]
                        const int* __restrict__ hkl,          // [N,3]
                        const float* __restrict__ wavelength, // [N]
                        const float* __restrict__ dmin,       // [N_ASU]
                        const float* __restrict__ B,          // [N_ASU,3,3]
                        const int* __restrict__ refl_table,   // [N_ASU,G,G,G]
                        float* __restrict__ out,              // [30*N] f32
                        int N)
{
    // Staging buffers: per-row strided writes (conflict-free: strides 15,5 odd)
    __shared__ float s_hkl[BLK * 15];
    __shared__ float s_wl [BLK * 5];
    __shared__ float s_d  [BLK * 5];
    __shared__ float s_rid[BLK * 5];

    const int t  = threadIdx.x;
    const int i0 = blockIdx.x * BLK;
    const int i  = i0 + t;

    if (i < N) {
        const int asu = asu_id[i];
        const int h = hkl[3 * i + 0];
        const int k = hkl[3 * i + 1];
        const int l = hkl[3 * i + 2];
        const bool mask = (h | k | l) != 0;

        int g = gcd2(gcd2(abs(h), abs(k)), abs(l));
        const int ns = max(g, 1);
        const int h0 = h / ns;
        const int k0 = k / ns;
        const int l0 = l / ns;

        const float wl0 = wavelength[i] * (float)ns;
        const float dmin_g = __ldg(&dmin[asu]);

        const float* Ba = B + 9 * asu;
        const float h0f = (float)h0, k0f = (float)k0, l0f = (float)l0;
        const float s0 = __ldg(&Ba[0]) * h0f + __ldg(&Ba[1]) * k0f + __ldg(&Ba[2]) * l0f;
        const float s1 = __ldg(&Ba[3]) * h0f + __ldg(&Ba[4]) * k0f + __ldg(&Ba[5]) * l0f;
        const float s2 = __ldg(&Ba[6]) * h0f + __ldg(&Ba[7]) * k0f + __ldg(&Ba[8]) * l0f;
        const float nrm = __fsqrt_rn(s0 * s0 + s1 * s1 + s2 * s2);
        const float d0  = __fdiv_rn(1.0f, fmaxf(nrm, 1e-6f));

        const float n_max = fminf(floorf(__fdiv_rn(d0, dmin_g)),
                                  floorf(__fdiv_rn(wl0, WMIN)));
        const float n_min = floorf(__fdiv_rn(wl0, WMAX)) + 1.0f;

        const int table_base = asu * (GDIM * GDIM * GDIM);

#pragma unroll
        for (int m = 0; m < MAX_MULT; ++m) {
            float na = n_min + (float)m;
            if (na > n_max) na = 0.0f;
            int ni = (int)na;

            int ha = h0 * ni, ka = k0 * ni, la = l0 * ni;

            int ia = ha + HMAX, ib = ka + HMAX, ic = la + HMAX;
            bool valid = ((unsigned)ia < GDIM) & ((unsigned)ib < GDIM) & ((unsigned)ic < GDIM);
            int rid = -1;
            if (valid) {
                rid = __ldg(&refl_table[table_base + (ia * GDIM + ib) * GDIM + ic]);
            }

            const bool absent = rid < 0;
            float n_inv;
            if (absent) {
                ha = 0; ka = 0; la = 0;
                n_inv = 0.0f;
            } else {
                n_inv = __fdiv_rn(1.0f, fmaxf(na, 1e-6f));
            }
            float dall = d0 * n_inv;
            float wla  = wl0 * n_inv;

            float ridf = (float)rid;
            if (!mask) {
                ha = 0; ka = 0; la = 0;
                wla = 0.0f; dall = 0.0f; ridf = 0.0f;
            }

            s_hkl[t * 15 + m * 3 + 0] = (float)ha;
            s_hkl[t * 15 + m * 3 + 1] = (float)ka;
            s_hkl[t * 15 + m * 3 + 2] = (float)la;
            s_wl [t * 5 + m] = wla;
            s_d  [t * 5 + m] = dall;
            s_rid[t * 5 + m] = ridf;
        }
    }

    __syncthreads();

    // Coalesced copy-out. cnt = rows this block actually produced.
    const int cnt = min(BLK, N - i0);
    if (cnt <= 0) return;

    const long long nll = (long long)N;
    float* __restrict__ g_hkl = out + (long long)i0 * 15;
    float* __restrict__ g_wl  = out + 15 * nll + (long long)i0 * 5;
    float* __restrict__ g_d   = out + 20 * nll + (long long)i0 * 5;
    float* __restrict__ g_rid = out + 25 * nll + (long long)i0 * 5;

    const int n15 = cnt * 15;
    for (int idx = t; idx < n15; idx += BLK)
        g_hkl[idx] = s_hkl[idx];

    const int n5 = cnt * 5;
    for (int idx = t; idx < n5; idx += BLK) {
        g_wl [idx] = s_wl [idx];
        g_d  [idx] = s_d  [idx];
        g_rid[idx] = s_rid[idx];
    }
}

extern "C" void kernel_launch(void* const* d_in, const int* in_sizes, int n_in,
                              void* d_out, int out_size)
{
    const int*   asu_id     = (const int*)d_in[0];
    const int*   hkl        = (const int*)d_in[1];
    const float* wavelength = (const float*)d_in[2];
    const float* dmin       = (const float*)d_in[3];
    const float* B          = (const float*)d_in[4];
    const int*   refl_table = (const int*)d_in[5];

    const int N = in_sizes[0];
    float* out = (float*)d_out;

    const int blocks = (N + BLK - 1) / BLK;
    expand_harmonics_kernel<<<blocks, BLK>>>(asu_id, hkl, wavelength,
                                             dmin, B, refl_table, out, N);
}

// round 3
// speedup vs baseline: 3.3612x; 1.1360x over previous
#include <cuda_runtime.h>
#include <cstdint>

#define HMAX 60
#define GDIM 121           // 2*HMAX+1
#define MAX_MULT 5
#define RCP_WMIN (1.0f / 0.95f)
#define RCP_WMAX 0.8f      // 1/1.25
#define BLK 256

// Reciprocal table: 1.0f/i (rn-exact), index 0 unused (absent path forces 0)
__constant__ float c_recip[32] = {
    0.0f,       1.0f,       1.0f/2.0f,  1.0f/3.0f,  1.0f/4.0f,  1.0f/5.0f,
    1.0f/6.0f,  1.0f/7.0f,  1.0f/8.0f,  1.0f/9.0f,  1.0f/10.0f, 1.0f/11.0f,
    1.0f/12.0f, 1.0f/13.0f, 1.0f/14.0f, 1.0f/15.0f, 1.0f/16.0f, 1.0f/17.0f,
    1.0f/18.0f, 1.0f/19.0f, 1.0f/20.0f, 1.0f/21.0f, 1.0f/22.0f, 1.0f/23.0f,
    1.0f/24.0f, 1.0f/25.0f, 1.0f/26.0f, 1.0f/27.0f, 1.0f/28.0f, 1.0f/29.0f,
    1.0f/30.0f, 1.0f/31.0f
};

__device__ __forceinline__ int gcd2(int a, int b) {
    while (b != 0) { int t = a % b; a = b; b = t; }
    return a;
}

__global__ void __launch_bounds__(BLK)
expand_harmonics_kernel(const int* __restrict__ asu_id,       // [N]
                        const int* __restrict__ hkl,          // [N,3]
                        const float* __restrict__ wavelength, // [N]
                        const float* __restrict__ dmin,       // [N_ASU]
                        const float* __restrict__ B,          // [N_ASU,3,3]
                        const int* __restrict__ refl_table,   // [N_ASU,G,G,G]
                        float* __restrict__ out,              // [30*N] f32
                        int N)
{
    __shared__ __align__(16) float s_hkl[BLK * 15];
    __shared__ __align__(16) float s_wl [BLK * 5];
    __shared__ __align__(16) float s_d  [BLK * 5];
    __shared__ __align__(16) float s_rid[BLK * 5];

    const int t  = threadIdx.x;
    const int i0 = blockIdx.x * BLK;
    const int i  = i0 + t;

    if (i < N) {
        const int asu = asu_id[i];
        const int h = hkl[3 * i + 0];
        const int k = hkl[3 * i + 1];
        const int l = hkl[3 * i + 2];
        const bool mask = (h | k | l) != 0;

        const int g  = gcd2(gcd2(abs(h), abs(k)), abs(l));
        const int ns = max(g, 1);
        const int h0 = h / ns;
        const int k0 = k / ns;
        const int l0 = l / ns;

        const float wl0 = wavelength[i] * (float)ns;

        const float* Ba = B + 9 * asu;
        const float h0f = (float)h0, k0f = (float)k0, l0f = (float)l0;
        const float s0 = __ldg(&Ba[0]) * h0f + __ldg(&Ba[1]) * k0f + __ldg(&Ba[2]) * l0f;
        const float s1 = __ldg(&Ba[3]) * h0f + __ldg(&Ba[4]) * k0f + __ldg(&Ba[5]) * l0f;
        const float s2 = __ldg(&Ba[6]) * h0f + __ldg(&Ba[7]) * k0f + __ldg(&Ba[8]) * l0f;
        const float nrm = __fsqrt_rn(s0 * s0 + s1 * s1 + s2 * s2);
        const float d0  = __fdividef(1.0f, fmaxf(nrm, 1e-6f));

        const float n_max = fminf(floorf(__fdividef(d0, __ldg(&dmin[asu]))),
                                  floorf(wl0 * RCP_WMIN));
        const float n_min = floorf(wl0 * RCP_WMAX) + 1.0f;

        // Hoisted lookup math: idx = center + ni*step
        const int center = asu * (GDIM * GDIM * GDIM)
                         + (HMAX * GDIM + HMAX) * GDIM + HMAX;
        const int step = h0 * (GDIM * GDIM) + k0 * GDIM + l0;
        const int max_abs = max(max(abs(h0), abs(k0)), abs(l0));

#pragma unroll
        for (int m = 0; m < MAX_MULT; ++m) {
            float na = n_min + (float)m;
            na = (na > n_max) ? 0.0f : na;
            int ni = (int)na;                 // integral, 0..~18

            const bool valid = (max_abs * ni) <= HMAX;
            int rid = -1;
            if (valid) rid = __ldg(&refl_table[center + ni * step]);

            const bool present = rid >= 0;    // absent covers: out-of-range,
                                              // table -1, na==0, and hkl==0
            const float n_inv = present ? c_recip[ni & 31] : 0.0f;
            const float haf = present ? h0f * na : 0.0f;   // exact int products
            const float kaf = present ? k0f * na : 0.0f;
            const float laf = present ? l0f * na : 0.0f;

            s_hkl[t * 15 + m * 3 + 0] = haf;
            s_hkl[t * 15 + m * 3 + 1] = kaf;
            s_hkl[t * 15 + m * 3 + 2] = laf;
            s_wl [t * 5 + m] = wl0 * n_inv;
            s_d  [t * 5 + m] = d0  * n_inv;
            s_rid[t * 5 + m] = mask ? (float)rid : 0.0f;
        }
    }

    __syncthreads();

    const int cnt = min(BLK, N - i0);
    if (cnt <= 0) return;

    const long long nll = (long long)N;
    float* __restrict__ g_hkl = out + (long long)i0 * 15;
    float* __restrict__ g_wl  = out + 15 * nll + (long long)i0 * 5;
    float* __restrict__ g_d   = out + 20 * nll + (long long)i0 * 5;
    float* __restrict__ g_rid = out + 25 * nll + (long long)i0 * 5;

    const bool vec_ok = (cnt == BLK) && ((N & 3) == 0) &&
                        ((((uintptr_t)out) & 15) == 0);

    if (vec_ok) {
        // 15*BLK/4 = 960 float4, 5*BLK/4 = 320 float4
        const float4* s4h = (const float4*)s_hkl;
        float4* g4h = (float4*)g_hkl;
#pragma unroll
        for (int idx = t; idx < (BLK * 15) / 4; idx += BLK)
            g4h[idx] = s4h[idx];

        const float4* s4w = (const float4*)s_wl;
        const float4* s4d = (const float4*)s_d;
        const float4* s4r = (const float4*)s_rid;
        float4* g4w = (float4*)g_wl;
        float4* g4d = (float4*)g_d;
        float4* g4r = (float4*)g_rid;
#pragma unroll
        for (int idx = t; idx < (BLK * 5) / 4; idx += BLK) {
            g4w[idx] = s4w[idx];
            g4d[idx] = s4d[idx];
            g4r[idx] = s4r[idx];
        }
    } else {
        const int n15 = cnt * 15;
        for (int idx = t; idx < n15; idx += BLK)
            g_hkl[idx] = s_hkl[idx];
        const int n5 = cnt * 5;
        for (int idx = t; idx < n5; idx += BLK) {
            g_wl [idx] = s_wl [idx];
            g_d  [idx] = s_d  [idx];
            g_rid[idx] = s_rid[idx];
        }
    }
}

extern "C" void kernel_launch(void* const* d_in, const int* in_sizes, int n_in,
                              void* d_out, int out_size)
{
    const int*   asu_id     = (const int*)d_in[0];
    const int*   hkl        = (const int*)d_in[1];
    const float* wavelength = (const float*)d_in[2];
    const float* dmin       = (const float*)d_in[3];
    const float* B          = (const float*)d_in[4];
    const int*   refl_table = (const int*)d_in[5];

    const int N = in_sizes[0];
    float* out = (float*)d_out;

    const int blocks = (N + BLK - 1) / BLK;
    expand_harmonics_kernel<<<blocks, BLK>>>(asu_id, hkl, wavelength,
                                             dmin, B, refl_table, out, N);
}